// round 2
// baseline (speedup 1.0000x reference)
#include <cuda_runtime.h>
#include <cuda_bf16.h>
#include <math.h>

// ---------------------------------------------------------------------------
// Net_85263690760638: 3x GINConv(eps=0) + ELU, scatter-mean pool, 3-layer MLP.
// N=100000 nodes, E=3200000 edges, F=64, G=512.
// NOTE: JAX default (no x64) => edge_index and batch are int32 on device.
// ---------------------------------------------------------------------------

#define MAXN 131072
#define MAXG 1024

__device__ __align__(16) float g_agg [MAXN * 64];
__device__ __align__(16) float g_bufA[MAXN * 64];
__device__ __align__(16) float g_bufB[MAXN * 64];
__device__ __align__(16) float g_pool[MAXG * 64];
__device__ __align__(16) float g_cnt [MAXG];

__device__ __forceinline__ void red4(float* addr, float4 v) {
    asm volatile("red.global.add.v4.f32 [%0], {%1,%2,%3,%4};"
                 :: "l"(addr), "f"(v.x), "f"(v.y), "f"(v.z), "f"(v.w)
                 : "memory");
}

__device__ __forceinline__ float elu(float x) {
    return x > 0.f ? x : expm1f(x);
}

// ------------------------- edge scatter: agg[dst] += x[src] ----------------
template <int FI>
__global__ void scatter_kernel(const float* __restrict__ x,
                               const int* __restrict__ src,
                               const int* __restrict__ dst,
                               float* __restrict__ agg, int E) {
    constexpr unsigned GP = FI / 4;  // float4 groups per edge (power of two)
    unsigned long long total = (unsigned long long)E * GP;
    unsigned long long i = (unsigned long long)blockIdx.x * blockDim.x + threadIdx.x;
    if (i >= total) return;
    unsigned e = (unsigned)(i / GP);
    unsigned g = (unsigned)(i % GP);
    unsigned s = (unsigned)src[e];
    unsigned d = (unsigned)dst[e];
    float4 v = *reinterpret_cast<const float4*>(x + (size_t)s * FI + g * 4u);
    red4(agg + (size_t)d * FI + g * 4u, v);
}

// -------------------- fused (in+agg)@W + b, ELU -----------------------------
template <int FI, int FO>
__global__ void linear_elu_kernel(const float* __restrict__ in,
                                  const float* __restrict__ agg,
                                  const float* __restrict__ W,
                                  const float* __restrict__ b,
                                  float* __restrict__ out, int N) {
    constexpr int ROWS = 256 / FO;
    __shared__ float Ws[FI * FO];
    __shared__ float bs[FO];
    __shared__ float s[ROWS][FI];

    for (int i = threadIdx.x; i < FI * FO; i += 256) Ws[i] = W[i];
    if (threadIdx.x < FO) bs[threadIdx.x] = b[threadIdx.x];

    int r  = threadIdx.x / FO;
    int fo = threadIdx.x % FO;
    int row = blockIdx.x * ROWS + r;

    if (row < N) {
        #pragma unroll
        for (int k = fo; k < FI; k += FO)
            s[r][k] = in[(size_t)row * FI + k] + agg[(size_t)row * FI + k];
    }
    __syncthreads();

    if (row < N) {
        float acc = bs[fo];
        #pragma unroll
        for (int k = 0; k < FI; k++)
            acc = fmaf(s[r][k], Ws[k * FO + fo], acc);
        out[(size_t)row * FO + fo] = elu(acc);
    }
}

// ------------------------- pooling: sums + counts ---------------------------
__global__ void pool_kernel(const float* __restrict__ h,
                            const int* __restrict__ batch,
                            float* __restrict__ pool,
                            float* __restrict__ cnt, int N) {
    unsigned long long i = (unsigned long long)blockIdx.x * blockDim.x + threadIdx.x;
    unsigned long long total = (unsigned long long)N * 16;
    if (i >= total) return;
    unsigned node = (unsigned)(i >> 4);
    unsigned f4   = (unsigned)(i & 15u) * 4u;
    unsigned bg   = (unsigned)batch[node];
    float4 v = *reinterpret_cast<const float4*>(h + (size_t)node * 64 + f4);
    red4(pool + (size_t)bg * 64 + f4, v);
    if (f4 == 0) atomicAdd(&cnt[bg], 1.0f);
}

// ------------------------- final 64->64->32->1 MLP --------------------------
__global__ void final_mlp_kernel(const float* __restrict__ pool,
                                 const float* __restrict__ cnt,
                                 const float* __restrict__ Wf1, const float* __restrict__ bf1,
                                 const float* __restrict__ Wf2, const float* __restrict__ bf2,
                                 const float* __restrict__ Wf3, const float* __restrict__ bf3,
                                 float* __restrict__ out, int G) {
    __shared__ float W1s[64 * 64];
    __shared__ float W2s[64 * 32];
    __shared__ float W3s[32];
    __shared__ float b1s[64];
    __shared__ float b2s[32];

    for (int i = threadIdx.x; i < 64 * 64; i += 256) W1s[i] = Wf1[i];
    for (int i = threadIdx.x; i < 64 * 32; i += 256) W2s[i] = Wf2[i];
    if (threadIdx.x < 32) W3s[threadIdx.x] = Wf3[threadIdx.x];
    if (threadIdx.x < 64) b1s[threadIdx.x] = bf1[threadIdx.x];
    if (threadIdx.x < 32) b2s[threadIdx.x] = bf2[threadIdx.x];
    __syncthreads();

    int g = blockIdx.x * blockDim.x + threadIdx.x;
    if (g >= G) return;

    float inv = 1.0f / fmaxf(cnt[g], 1.0f);
    float m[64];
    #pragma unroll
    for (int k = 0; k < 64; k++) m[k] = pool[(size_t)g * 64 + k] * inv;

    float h2v[32];
    #pragma unroll
    for (int j = 0; j < 32; j++) h2v[j] = b2s[j];

    for (int fo = 0; fo < 64; fo++) {
        float a = b1s[fo];
        #pragma unroll
        for (int k = 0; k < 64; k++) a = fmaf(m[k], W1s[k * 64 + fo], a);
        a = elu(a);
        #pragma unroll
        for (int j = 0; j < 32; j++) h2v[j] = fmaf(a, W2s[fo * 32 + j], h2v[j]);
    }

    float o = bf3[0];
    #pragma unroll
    for (int j = 0; j < 32; j++) {
        float t = elu(h2v[j]);
        o = fmaf(t, W3s[j], o);
    }
    out[g] = o;
}

// ---------------------------------------------------------------------------
extern "C" void kernel_launch(void* const* d_in, const int* in_sizes, int n_in,
                              void* d_out, int out_size) {
    const float* x     = (const float*)d_in[0];
    const int*   ei    = (const int*)d_in[1];     // int32 (JAX default, no x64)
    const int*   batch = (const int*)d_in[2];     // int32
    // d_in[3] = num_graphs scalar (unused; G = out_size)
    const float* W1  = (const float*)d_in[4];
    const float* b1  = (const float*)d_in[5];
    const float* W2  = (const float*)d_in[6];
    const float* b2  = (const float*)d_in[7];
    const float* W3  = (const float*)d_in[8];
    const float* b3  = (const float*)d_in[9];
    const float* Wf1 = (const float*)d_in[10];
    const float* bf1 = (const float*)d_in[11];
    const float* Wf2 = (const float*)d_in[12];
    const float* bf2 = (const float*)d_in[13];
    const float* Wf3 = (const float*)d_in[14];
    const float* bf3 = (const float*)d_in[15];

    const int N = in_sizes[0] / 64;
    const int E = in_sizes[1] / 2;
    const int G = out_size;

    const int* src = ei;
    const int* dst = ei + E;

    float *agg, *bufA, *bufB, *pool, *cnt;
    cudaGetSymbolAddress((void**)&agg,  g_agg);
    cudaGetSymbolAddress((void**)&bufA, g_bufA);
    cudaGetSymbolAddress((void**)&bufB, g_bufB);
    cudaGetSymbolAddress((void**)&pool, g_pool);
    cudaGetSymbolAddress((void**)&cnt,  g_cnt);

    const int TPB = 256;
    unsigned long long t64 = (unsigned long long)E * 16;  // FI=64 scatter threads
    unsigned long long t32 = (unsigned long long)E * 8;   // FI=32 scatter threads
    int blk64 = (int)((t64 + TPB - 1) / TPB);
    int blk32 = (int)((t32 + TPB - 1) / TPB);

    // ---- Layer 1: 64 -> 32 ----
    cudaMemsetAsync(agg, 0, (size_t)N * 64 * sizeof(float));
    scatter_kernel<64><<<blk64, TPB>>>(x, src, dst, agg, E);
    linear_elu_kernel<64, 32><<<(N + 7) / 8, TPB>>>(x, agg, W1, b1, bufA, N);

    // ---- Layer 2: 32 -> 64 ----
    cudaMemsetAsync(agg, 0, (size_t)N * 32 * sizeof(float));
    scatter_kernel<32><<<blk32, TPB>>>(bufA, src, dst, agg, E);
    linear_elu_kernel<32, 64><<<(N + 3) / 4, TPB>>>(bufA, agg, W2, b2, bufB, N);

    // ---- Layer 3: 64 -> 64 ----
    cudaMemsetAsync(agg, 0, (size_t)N * 64 * sizeof(float));
    scatter_kernel<64><<<blk64, TPB>>>(bufB, src, dst, agg, E);
    linear_elu_kernel<64, 64><<<(N + 3) / 4, TPB>>>(bufB, agg, W3, b3, bufA, N);

    // ---- Pooling (scatter-mean) ----
    cudaMemsetAsync(pool, 0, (size_t)G * 64 * sizeof(float));
    cudaMemsetAsync(cnt,  0, (size_t)G * sizeof(float));
    unsigned long long tp = (unsigned long long)N * 16;
    pool_kernel<<<(int)((tp + TPB - 1) / TPB), TPB>>>(bufA, batch, pool, cnt, N);

    // ---- Final MLP ----
    final_mlp_kernel<<<(G + TPB - 1) / TPB, TPB>>>(pool, cnt, Wf1, bf1, Wf2, bf2,
                                                   Wf3, bf3, (float*)d_out, G);
}

// round 3
// speedup vs baseline: 1.7314x; 1.7314x over previous
#include <cuda_runtime.h>
#include <cuda_bf16.h>
#include <math.h>

// ---------------------------------------------------------------------------
// Net_85263690760638: 3x GINConv(eps=0)+ELU, scatter-mean pool, 3-layer MLP.
// N=100000, E=3200000, F=64, G=512. edge_index/batch are int32 on device.
//
// R3 design: CSR-by-dst built per call (no float atomics in aggregation),
// transform-first for layer 1 (width-32 aggregation), warp-per-node fused
// gather+GEMV kernels with shuffle-broadcast, pooling fused into layer 3.
// ---------------------------------------------------------------------------

#define MAXN 131072
#define MAXE 4194304
#define MAXG 1024
#define FULL 0xffffffffu

__device__ __align__(16) float g_bufA[MAXN * 64];   // y (N x 32), later h2 (N x 64)
__device__ __align__(16) float g_bufB[MAXN * 64];   // h1 (N x 32)
__device__ __align__(16) float g_pool[MAXG * 64];
__device__ __align__(16) float g_cnt [MAXG];
__device__ int g_deg   [MAXN];
__device__ int g_offs  [MAXN];
__device__ int g_cursor[MAXN];
__device__ int g_bsums [256];
__device__ int g_csr   [MAXE];

__device__ __forceinline__ float elu(float x) { return x > 0.f ? x : expm1f(x); }

__device__ __forceinline__ void red2(float* addr, float vx, float vy) {
    asm volatile("red.global.add.v2.f32 [%0], {%1,%2};"
                 :: "l"(addr), "f"(vx), "f"(vy) : "memory");
}

// ============================ CSR construction ==============================
__global__ void count_deg_kernel(const int* __restrict__ dst, int* __restrict__ deg, int E) {
    int e = blockIdx.x * blockDim.x + threadIdx.x;
    if (e < E) atomicAdd(&deg[dst[e]], 1);
}

__global__ void scan_block_kernel(const int* __restrict__ deg, int* __restrict__ excl,
                                  int* __restrict__ bsums, int N) {
    __shared__ int s[1024];
    int i = blockIdx.x * 1024 + threadIdx.x;
    int v = (i < N) ? deg[i] : 0;
    s[threadIdx.x] = v;
    __syncthreads();
    #pragma unroll
    for (int off = 1; off < 1024; off <<= 1) {
        int t = (threadIdx.x >= off) ? s[threadIdx.x - off] : 0;
        __syncthreads();
        s[threadIdx.x] += t;
        __syncthreads();
    }
    if (i < N) excl[i] = s[threadIdx.x] - v;
    if (threadIdx.x == 1023) bsums[blockIdx.x] = s[1023];
}

__global__ void scan_sums_kernel(int* bsums, int nb) {
    if (threadIdx.x == 0 && blockIdx.x == 0) {
        int run = 0;
        for (int i = 0; i < nb; i++) { int t = bsums[i]; bsums[i] = run; run += t; }
    }
}

__global__ void add_off_kernel(int* __restrict__ excl, const int* __restrict__ bsums, int N) {
    int i = blockIdx.x * blockDim.x + threadIdx.x;
    if (i < N) excl[i] += bsums[i >> 10];
}

__global__ void fill_csr_kernel(const int* __restrict__ src, const int* __restrict__ dst,
                                int* __restrict__ cursor, int* __restrict__ csr, int E) {
    int e = blockIdx.x * blockDim.x + threadIdx.x;
    if (e < E) {
        int p = atomicAdd(&cursor[dst[e]], 1);
        csr[p] = src[e];
    }
}

// ===================== gather helpers (warp-per-node) =======================
__device__ __forceinline__ float gather32(const float* __restrict__ h,
                                          const int* __restrict__ csr,
                                          int start, int d, int lane) {
    float a0 = 0.f, a1 = 0.f, a2 = 0.f, a3 = 0.f;
    int base = 0;
    while (base + 32 <= d) {
        int idx = csr[start + base + lane];
        #pragma unroll
        for (int j = 0; j < 32; j += 4) {
            int n0 = __shfl_sync(FULL, idx, j);
            int n1 = __shfl_sync(FULL, idx, j + 1);
            int n2 = __shfl_sync(FULL, idx, j + 2);
            int n3 = __shfl_sync(FULL, idx, j + 3);
            a0 += h[(size_t)n0 * 32 + lane];
            a1 += h[(size_t)n1 * 32 + lane];
            a2 += h[(size_t)n2 * 32 + lane];
            a3 += h[(size_t)n3 * 32 + lane];
        }
        base += 32;
    }
    int rem = d - base;
    if (rem > 0) {
        int idx = csr[start + base + ((lane < rem) ? lane : 0)];
        for (int j = 0; j < rem; j++) {
            int nb = __shfl_sync(FULL, idx, j);
            a0 += h[(size_t)nb * 32 + lane];
        }
    }
    return (a0 + a1) + (a2 + a3);
}

__device__ __forceinline__ float2 gather64(const float* __restrict__ h,
                                           const int* __restrict__ csr,
                                           int start, int d, int lane) {
    float2 a0 = {0.f, 0.f}, a1 = {0.f, 0.f}, a2 = {0.f, 0.f}, a3 = {0.f, 0.f};
    int base = 0;
    while (base + 32 <= d) {
        int idx = csr[start + base + lane];
        #pragma unroll
        for (int j = 0; j < 32; j += 4) {
            int n0 = __shfl_sync(FULL, idx, j);
            int n1 = __shfl_sync(FULL, idx, j + 1);
            int n2 = __shfl_sync(FULL, idx, j + 2);
            int n3 = __shfl_sync(FULL, idx, j + 3);
            float2 v0 = *(const float2*)(h + (size_t)n0 * 64 + lane * 2);
            float2 v1 = *(const float2*)(h + (size_t)n1 * 64 + lane * 2);
            float2 v2 = *(const float2*)(h + (size_t)n2 * 64 + lane * 2);
            float2 v3 = *(const float2*)(h + (size_t)n3 * 64 + lane * 2);
            a0.x += v0.x; a0.y += v0.y;
            a1.x += v1.x; a1.y += v1.y;
            a2.x += v2.x; a2.y += v2.y;
            a3.x += v3.x; a3.y += v3.y;
        }
        base += 32;
    }
    int rem = d - base;
    if (rem > 0) {
        int idx = csr[start + base + ((lane < rem) ? lane : 0)];
        for (int j = 0; j < rem; j++) {
            int nb = __shfl_sync(FULL, idx, j);
            float2 v = *(const float2*)(h + (size_t)nb * 64 + lane * 2);
            a0.x += v.x; a0.y += v.y;
        }
    }
    float2 r;
    r.x = (a0.x + a1.x) + (a2.x + a3.x);
    r.y = (a0.y + a1.y) + (a2.y + a3.y);
    return r;
}

// ========================= layer kernels ====================================
// y = x @ W1   (64 -> 32), warp per row, W1 broadcast via smem.
__global__ void linear1_kernel(const float* __restrict__ x, const float* __restrict__ W1,
                               float* __restrict__ y, int N) {
    __shared__ float Ws[64 * 32];
    for (int i = threadIdx.x; i < 64 * 32; i += blockDim.x) Ws[i] = W1[i];
    __syncthreads();
    int warp = (blockIdx.x * blockDim.x + threadIdx.x) >> 5;
    int lane = threadIdx.x & 31;
    if (warp >= N) return;
    float2 xv = *(const float2*)(x + (size_t)warp * 64 + lane * 2);
    float acc = 0.f;
    #pragma unroll
    for (int k = 0; k < 64; k++) {
        float bv = __shfl_sync(FULL, (k & 1) ? xv.y : xv.x, k >> 1);
        acc = fmaf(bv, Ws[k * 32 + lane], acc);
    }
    y[(size_t)warp * 32 + lane] = acc;
}

// h1 = elu(y + A@y + b1)   (width 32, no GEMV needed — transform-first)
__global__ void gin_layer1_kernel(const float* __restrict__ y,
                                  const int* __restrict__ offs, const int* __restrict__ deg,
                                  const int* __restrict__ csr,
                                  const float* __restrict__ b1,
                                  float* __restrict__ h1, int N) {
    int warp = (blockIdx.x * blockDim.x + threadIdx.x) >> 5;
    int lane = threadIdx.x & 31;
    if (warp >= N) return;
    float agg = gather32(y, csr, offs[warp], deg[warp], lane);
    float v = y[(size_t)warp * 32 + lane] + agg + b1[lane];
    h1[(size_t)warp * 32 + lane] = elu(v);
}

// h2 = elu((h1 + A@h1) @ W2 + b2)   (32 -> 64)
__global__ void gin_layer2_kernel(const float* __restrict__ h1,
                                  const int* __restrict__ offs, const int* __restrict__ deg,
                                  const int* __restrict__ csr,
                                  const float* __restrict__ W2, const float* __restrict__ b2,
                                  float* __restrict__ h2, int N) {
    __shared__ float Ws[32 * 64];
    __shared__ float bs[64];
    for (int i = threadIdx.x; i < 32 * 64; i += blockDim.x) Ws[i] = W2[i];
    if (threadIdx.x < 64) bs[threadIdx.x] = b2[threadIdx.x];
    __syncthreads();
    int warp = (blockIdx.x * blockDim.x + threadIdx.x) >> 5;
    int lane = threadIdx.x & 31;
    if (warp >= N) return;
    float agg = gather32(h1, csr, offs[warp], deg[warp], lane);
    float s = h1[(size_t)warp * 32 + lane] + agg;
    float o0 = bs[2 * lane], o1 = bs[2 * lane + 1];
    const float2* Wv = (const float2*)Ws;
    #pragma unroll
    for (int k = 0; k < 32; k++) {
        float bv = __shfl_sync(FULL, s, k);
        float2 w = Wv[k * 32 + lane];
        o0 = fmaf(bv, w.x, o0);
        o1 = fmaf(bv, w.y, o1);
    }
    float2 out;
    out.x = elu(o0);
    out.y = elu(o1);
    *(float2*)(h2 + (size_t)warp * 64 + lane * 2) = out;
}

// h3 = elu((h2 + A@h2) @ W3 + b3), fused pooling: pool[batch] += h3, cnt++.
__global__ void gin_layer3_pool_kernel(const float* __restrict__ h2,
                                       const int* __restrict__ offs, const int* __restrict__ deg,
                                       const int* __restrict__ csr,
                                       const float* __restrict__ W3, const float* __restrict__ b3,
                                       const int* __restrict__ batch,
                                       float* __restrict__ pool, float* __restrict__ cnt, int N) {
    __shared__ float Ws[64 * 64];
    __shared__ float bs[64];
    for (int i = threadIdx.x; i < 64 * 64; i += blockDim.x) Ws[i] = W3[i];
    if (threadIdx.x < 64) bs[threadIdx.x] = b3[threadIdx.x];
    __syncthreads();
    int warp = (blockIdx.x * blockDim.x + threadIdx.x) >> 5;
    int lane = threadIdx.x & 31;
    if (warp >= N) return;
    float2 agg = gather64(h2, csr, offs[warp], deg[warp], lane);
    float2 own = *(const float2*)(h2 + (size_t)warp * 64 + lane * 2);
    float sx = own.x + agg.x;
    float sy = own.y + agg.y;
    float o0 = bs[2 * lane], o1 = bs[2 * lane + 1];
    const float2* Wv = (const float2*)Ws;
    #pragma unroll
    for (int k = 0; k < 64; k++) {
        float bv = __shfl_sync(FULL, (k & 1) ? sy : sx, k >> 1);
        float2 w = Wv[k * 32 + lane];
        o0 = fmaf(bv, w.x, o0);
        o1 = fmaf(bv, w.y, o1);
    }
    o0 = elu(o0);
    o1 = elu(o1);
    int g = batch[warp];
    red2(pool + (size_t)g * 64 + lane * 2, o0, o1);
    if (lane == 0) atomicAdd(&cnt[g], 1.0f);
}

// ------------------------- final 64->64->32->1 MLP --------------------------
__global__ void final_mlp_kernel(const float* __restrict__ pool,
                                 const float* __restrict__ cnt,
                                 const float* __restrict__ Wf1, const float* __restrict__ bf1,
                                 const float* __restrict__ Wf2, const float* __restrict__ bf2,
                                 const float* __restrict__ Wf3, const float* __restrict__ bf3,
                                 float* __restrict__ out, int G) {
    __shared__ float W1s[64 * 64];
    __shared__ float W2s[64 * 32];
    __shared__ float W3s[32];
    __shared__ float b1s[64];
    __shared__ float b2s[32];
    for (int i = threadIdx.x; i < 64 * 64; i += 256) W1s[i] = Wf1[i];
    for (int i = threadIdx.x; i < 64 * 32; i += 256) W2s[i] = Wf2[i];
    if (threadIdx.x < 32) W3s[threadIdx.x] = Wf3[threadIdx.x];
    if (threadIdx.x < 64) b1s[threadIdx.x] = bf1[threadIdx.x];
    if (threadIdx.x < 32) b2s[threadIdx.x] = bf2[threadIdx.x];
    __syncthreads();

    int g = blockIdx.x * blockDim.x + threadIdx.x;
    if (g >= G) return;

    float inv = 1.0f / fmaxf(cnt[g], 1.0f);
    float m[64];
    #pragma unroll
    for (int k = 0; k < 64; k++) m[k] = pool[(size_t)g * 64 + k] * inv;

    float h2v[32];
    #pragma unroll
    for (int j = 0; j < 32; j++) h2v[j] = b2s[j];

    for (int fo = 0; fo < 64; fo++) {
        float a = b1s[fo];
        #pragma unroll
        for (int k = 0; k < 64; k++) a = fmaf(m[k], W1s[k * 64 + fo], a);
        a = elu(a);
        #pragma unroll
        for (int j = 0; j < 32; j++) h2v[j] = fmaf(a, W2s[fo * 32 + j], h2v[j]);
    }

    float o = bf3[0];
    #pragma unroll
    for (int j = 0; j < 32; j++) {
        float t = elu(h2v[j]);
        o = fmaf(t, W3s[j], o);
    }
    out[g] = o;
}

// ---------------------------------------------------------------------------
extern "C" void kernel_launch(void* const* d_in, const int* in_sizes, int n_in,
                              void* d_out, int out_size) {
    const float* x     = (const float*)d_in[0];
    const int*   ei    = (const int*)d_in[1];
    const int*   batch = (const int*)d_in[2];
    const float* W1  = (const float*)d_in[4];
    const float* b1  = (const float*)d_in[5];
    const float* W2  = (const float*)d_in[6];
    const float* b2  = (const float*)d_in[7];
    const float* W3  = (const float*)d_in[8];
    const float* b3  = (const float*)d_in[9];
    const float* Wf1 = (const float*)d_in[10];
    const float* bf1 = (const float*)d_in[11];
    const float* Wf2 = (const float*)d_in[12];
    const float* bf2 = (const float*)d_in[13];
    const float* Wf3 = (const float*)d_in[14];
    const float* bf3 = (const float*)d_in[15];

    const int N = in_sizes[0] / 64;
    const int E = in_sizes[1] / 2;
    const int G = out_size;

    const int* src = ei;
    const int* dst = ei + E;

    float *bufA, *bufB, *pool, *cnt;
    int *deg, *offs, *cursor, *bsums, *csr;
    cudaGetSymbolAddress((void**)&bufA,   g_bufA);
    cudaGetSymbolAddress((void**)&bufB,   g_bufB);
    cudaGetSymbolAddress((void**)&pool,   g_pool);
    cudaGetSymbolAddress((void**)&cnt,    g_cnt);
    cudaGetSymbolAddress((void**)&deg,    g_deg);
    cudaGetSymbolAddress((void**)&offs,   g_offs);
    cudaGetSymbolAddress((void**)&cursor, g_cursor);
    cudaGetSymbolAddress((void**)&bsums,  g_bsums);
    cudaGetSymbolAddress((void**)&csr,    g_csr);

    const int TPB = 256;
    const int eblk = (E + TPB - 1) / TPB;
    const int nblk1024 = (N + 1023) / 1024;
    const int nodeblk = (N + 7) / 8;  // warp per node, 8 warps per block

    // ---- CSR build (by dst) ----
    cudaMemsetAsync(deg, 0, (size_t)N * sizeof(int));
    count_deg_kernel<<<eblk, TPB>>>(dst, deg, E);
    scan_block_kernel<<<nblk1024, 1024>>>(deg, offs, bsums, N);
    scan_sums_kernel<<<1, 32>>>(bsums, nblk1024);
    add_off_kernel<<<(N + TPB - 1) / TPB, TPB>>>(offs, bsums, N);
    cudaMemcpyAsync(cursor, offs, (size_t)N * sizeof(int), cudaMemcpyDeviceToDevice);
    fill_csr_kernel<<<eblk, TPB>>>(src, dst, cursor, csr, E);

    // ---- Layer 1 (transform-first): y = x@W1; h1 = elu(y + A@y + b1) ----
    linear1_kernel<<<nodeblk, TPB>>>(x, W1, bufA, N);
    gin_layer1_kernel<<<nodeblk, TPB>>>(bufA, offs, deg, csr, b1, bufB, N);

    // ---- Layer 2: h2 = elu((h1 + A@h1)@W2 + b2) ----
    gin_layer2_kernel<<<nodeblk, TPB>>>(bufB, offs, deg, csr, W2, b2, bufA, N);

    // ---- Layer 3 + pooling ----
    cudaMemsetAsync(pool, 0, (size_t)G * 64 * sizeof(float));
    cudaMemsetAsync(cnt,  0, (size_t)G * sizeof(float));
    gin_layer3_pool_kernel<<<nodeblk, TPB>>>(bufA, offs, deg, csr, W3, b3, batch,
                                             pool, cnt, N);

    // ---- Final MLP ----
    final_mlp_kernel<<<(G + TPB - 1) / TPB, TPB>>>(pool, cnt, Wf1, bf1, Wf2, bf2,
                                                   Wf3, bf3, (float*)d_out, G);
}

// round 4
// speedup vs baseline: 1.7665x; 1.0203x over previous
#include <cuda_runtime.h>
#include <cuda_bf16.h>
#include <math.h>

// ---------------------------------------------------------------------------
// Net_85263690760638: 3x GINConv(eps=0)+ELU, scatter-mean pool, 3-layer MLP.
// N=100000, E=3200000, F=64, G=512. edge_index/batch are int32 on device.
//
// R4: fix remainder-path MLP=1 in gathers (8-wide in-flight loads for all
// degrees), __ldg on node rows, cursor fused into add_off.
// ---------------------------------------------------------------------------

#define MAXN 131072
#define MAXE 4194304
#define MAXG 1024
#define FULL 0xffffffffu

__device__ __align__(16) float g_bufA[MAXN * 64];
__device__ __align__(16) float g_bufB[MAXN * 64];
__device__ __align__(16) float g_pool[MAXG * 64];
__device__ __align__(16) float g_cnt [MAXG];
__device__ int g_deg   [MAXN];
__device__ int g_offs  [MAXN];
__device__ int g_cursor[MAXN];
__device__ int g_bsums [256];
__device__ int g_csr   [MAXE];

__device__ __forceinline__ float elu(float x) { return x > 0.f ? x : expm1f(x); }

__device__ __forceinline__ void red2(float* addr, float vx, float vy) {
    asm volatile("red.global.add.v2.f32 [%0], {%1,%2};"
                 :: "l"(addr), "f"(vx), "f"(vy) : "memory");
}

// ============================ CSR construction ==============================
__global__ void count_deg_kernel(const int* __restrict__ dst, int* __restrict__ deg, int E) {
    int e = blockIdx.x * blockDim.x + threadIdx.x;
    if (e < E) atomicAdd(&deg[dst[e]], 1);
}

__global__ void scan_block_kernel(const int* __restrict__ deg, int* __restrict__ excl,
                                  int* __restrict__ bsums, int N) {
    __shared__ int s[1024];
    int i = blockIdx.x * 1024 + threadIdx.x;
    int v = (i < N) ? deg[i] : 0;
    s[threadIdx.x] = v;
    __syncthreads();
    #pragma unroll
    for (int off = 1; off < 1024; off <<= 1) {
        int t = (threadIdx.x >= off) ? s[threadIdx.x - off] : 0;
        __syncthreads();
        s[threadIdx.x] += t;
        __syncthreads();
    }
    if (i < N) excl[i] = s[threadIdx.x] - v;
    if (threadIdx.x == 1023) bsums[blockIdx.x] = s[1023];
}

__global__ void scan_sums_kernel(int* bsums, int nb) {
    if (threadIdx.x == 0 && blockIdx.x == 0) {
        int run = 0;
        for (int i = 0; i < nb; i++) { int t = bsums[i]; bsums[i] = run; run += t; }
    }
}

__global__ void add_off_kernel(int* __restrict__ excl, int* __restrict__ cursor,
                               const int* __restrict__ bsums, int N) {
    int i = blockIdx.x * blockDim.x + threadIdx.x;
    if (i < N) {
        int v = excl[i] + bsums[i >> 10];
        excl[i] = v;
        cursor[i] = v;
    }
}

__global__ void fill_csr_kernel(const int* __restrict__ src, const int* __restrict__ dst,
                                int* __restrict__ cursor, int* __restrict__ csr, int E) {
    int e = blockIdx.x * blockDim.x + threadIdx.x;
    if (e < E) {
        int p = atomicAdd(&cursor[dst[e]], 1);
        csr[p] = src[e];
    }
}

// ===================== gather helpers (warp-per-node) =======================
// High-MLP gathers: per-32 chunk with clamped idx load, 8-wide in-flight body.
__device__ __forceinline__ float gather32(const float* __restrict__ h,
                                          const int* __restrict__ csr,
                                          int start, int d, int lane) {
    float a0 = 0.f, a1 = 0.f, a2 = 0.f, a3 = 0.f;
    for (int base = 0; base < d; base += 32) {
        int m = d - base; if (m > 32) m = 32;
        int idx = csr[start + base + ((lane < m) ? lane : 0)];
        int j = 0;
        #pragma unroll 1
        for (; j + 8 <= m; j += 8) {
            int n0 = __shfl_sync(FULL, idx, j + 0);
            int n1 = __shfl_sync(FULL, idx, j + 1);
            int n2 = __shfl_sync(FULL, idx, j + 2);
            int n3 = __shfl_sync(FULL, idx, j + 3);
            int n4 = __shfl_sync(FULL, idx, j + 4);
            int n5 = __shfl_sync(FULL, idx, j + 5);
            int n6 = __shfl_sync(FULL, idx, j + 6);
            int n7 = __shfl_sync(FULL, idx, j + 7);
            float v0 = __ldg(h + (size_t)n0 * 32 + lane);
            float v1 = __ldg(h + (size_t)n1 * 32 + lane);
            float v2 = __ldg(h + (size_t)n2 * 32 + lane);
            float v3 = __ldg(h + (size_t)n3 * 32 + lane);
            float v4 = __ldg(h + (size_t)n4 * 32 + lane);
            float v5 = __ldg(h + (size_t)n5 * 32 + lane);
            float v6 = __ldg(h + (size_t)n6 * 32 + lane);
            float v7 = __ldg(h + (size_t)n7 * 32 + lane);
            a0 += v0 + v4;
            a1 += v1 + v5;
            a2 += v2 + v6;
            a3 += v3 + v7;
        }
        #pragma unroll 1
        for (; j + 2 <= m; j += 2) {
            int n0 = __shfl_sync(FULL, idx, j + 0);
            int n1 = __shfl_sync(FULL, idx, j + 1);
            a0 += __ldg(h + (size_t)n0 * 32 + lane);
            a1 += __ldg(h + (size_t)n1 * 32 + lane);
        }
        if (j < m) {
            int n0 = __shfl_sync(FULL, idx, j);
            a2 += __ldg(h + (size_t)n0 * 32 + lane);
        }
    }
    return (a0 + a1) + (a2 + a3);
}

__device__ __forceinline__ float2 gather64(const float* __restrict__ h,
                                           const int* __restrict__ csr,
                                           int start, int d, int lane) {
    float2 a0 = {0.f, 0.f}, a1 = {0.f, 0.f}, a2 = {0.f, 0.f}, a3 = {0.f, 0.f};
    const float2* h2 = (const float2*)h;
    for (int base = 0; base < d; base += 32) {
        int m = d - base; if (m > 32) m = 32;
        int idx = csr[start + base + ((lane < m) ? lane : 0)];
        int j = 0;
        #pragma unroll 1
        for (; j + 8 <= m; j += 8) {
            int n0 = __shfl_sync(FULL, idx, j + 0);
            int n1 = __shfl_sync(FULL, idx, j + 1);
            int n2 = __shfl_sync(FULL, idx, j + 2);
            int n3 = __shfl_sync(FULL, idx, j + 3);
            int n4 = __shfl_sync(FULL, idx, j + 4);
            int n5 = __shfl_sync(FULL, idx, j + 5);
            int n6 = __shfl_sync(FULL, idx, j + 6);
            int n7 = __shfl_sync(FULL, idx, j + 7);
            float2 v0 = __ldg(h2 + (size_t)n0 * 32 + lane);
            float2 v1 = __ldg(h2 + (size_t)n1 * 32 + lane);
            float2 v2 = __ldg(h2 + (size_t)n2 * 32 + lane);
            float2 v3 = __ldg(h2 + (size_t)n3 * 32 + lane);
            float2 v4 = __ldg(h2 + (size_t)n4 * 32 + lane);
            float2 v5 = __ldg(h2 + (size_t)n5 * 32 + lane);
            float2 v6 = __ldg(h2 + (size_t)n6 * 32 + lane);
            float2 v7 = __ldg(h2 + (size_t)n7 * 32 + lane);
            a0.x += v0.x + v4.x; a0.y += v0.y + v4.y;
            a1.x += v1.x + v5.x; a1.y += v1.y + v5.y;
            a2.x += v2.x + v6.x; a2.y += v2.y + v6.y;
            a3.x += v3.x + v7.x; a3.y += v3.y + v7.y;
        }
        #pragma unroll 1
        for (; j + 2 <= m; j += 2) {
            int n0 = __shfl_sync(FULL, idx, j + 0);
            int n1 = __shfl_sync(FULL, idx, j + 1);
            float2 v0 = __ldg(h2 + (size_t)n0 * 32 + lane);
            float2 v1 = __ldg(h2 + (size_t)n1 * 32 + lane);
            a0.x += v0.x; a0.y += v0.y;
            a1.x += v1.x; a1.y += v1.y;
        }
        if (j < m) {
            int n0 = __shfl_sync(FULL, idx, j);
            float2 v = __ldg(h2 + (size_t)n0 * 32 + lane);
            a2.x += v.x; a2.y += v.y;
        }
    }
    float2 r;
    r.x = (a0.x + a1.x) + (a2.x + a3.x);
    r.y = (a0.y + a1.y) + (a2.y + a3.y);
    return r;
}

// ========================= layer kernels ====================================
__global__ void linear1_kernel(const float* __restrict__ x, const float* __restrict__ W1,
                               float* __restrict__ y, int N) {
    __shared__ float Ws[64 * 32];
    for (int i = threadIdx.x; i < 64 * 32; i += blockDim.x) Ws[i] = W1[i];
    __syncthreads();
    int warp = (blockIdx.x * blockDim.x + threadIdx.x) >> 5;
    int lane = threadIdx.x & 31;
    if (warp >= N) return;
    float2 xv = *(const float2*)(x + (size_t)warp * 64 + lane * 2);
    float acc = 0.f;
    #pragma unroll
    for (int k = 0; k < 64; k++) {
        float bv = __shfl_sync(FULL, (k & 1) ? xv.y : xv.x, k >> 1);
        acc = fmaf(bv, Ws[k * 32 + lane], acc);
    }
    y[(size_t)warp * 32 + lane] = acc;
}

__global__ void gin_layer1_kernel(const float* __restrict__ y,
                                  const int* __restrict__ offs, const int* __restrict__ deg,
                                  const int* __restrict__ csr,
                                  const float* __restrict__ b1,
                                  float* __restrict__ h1, int N) {
    int warp = (blockIdx.x * blockDim.x + threadIdx.x) >> 5;
    int lane = threadIdx.x & 31;
    if (warp >= N) return;
    float agg = gather32(y, csr, offs[warp], deg[warp], lane);
    float v = y[(size_t)warp * 32 + lane] + agg + b1[lane];
    h1[(size_t)warp * 32 + lane] = elu(v);
}

__global__ void gin_layer2_kernel(const float* __restrict__ h1,
                                  const int* __restrict__ offs, const int* __restrict__ deg,
                                  const int* __restrict__ csr,
                                  const float* __restrict__ W2, const float* __restrict__ b2,
                                  float* __restrict__ h2, int N) {
    __shared__ float Ws[32 * 64];
    __shared__ float bs[64];
    for (int i = threadIdx.x; i < 32 * 64; i += blockDim.x) Ws[i] = W2[i];
    if (threadIdx.x < 64) bs[threadIdx.x] = b2[threadIdx.x];
    __syncthreads();
    int warp = (blockIdx.x * blockDim.x + threadIdx.x) >> 5;
    int lane = threadIdx.x & 31;
    if (warp >= N) return;
    float agg = gather32(h1, csr, offs[warp], deg[warp], lane);
    float s = h1[(size_t)warp * 32 + lane] + agg;
    float o0 = bs[2 * lane], o1 = bs[2 * lane + 1];
    const float2* Wv = (const float2*)Ws;
    #pragma unroll
    for (int k = 0; k < 32; k++) {
        float bv = __shfl_sync(FULL, s, k);
        float2 w = Wv[k * 32 + lane];
        o0 = fmaf(bv, w.x, o0);
        o1 = fmaf(bv, w.y, o1);
    }
    float2 out;
    out.x = elu(o0);
    out.y = elu(o1);
    *(float2*)(h2 + (size_t)warp * 64 + lane * 2) = out;
}

__global__ void gin_layer3_pool_kernel(const float* __restrict__ h2,
                                       const int* __restrict__ offs, const int* __restrict__ deg,
                                       const int* __restrict__ csr,
                                       const float* __restrict__ W3, const float* __restrict__ b3,
                                       const int* __restrict__ batch,
                                       float* __restrict__ pool, float* __restrict__ cnt, int N) {
    __shared__ float Ws[64 * 64];
    __shared__ float bs[64];
    for (int i = threadIdx.x; i < 64 * 64; i += blockDim.x) Ws[i] = W3[i];
    if (threadIdx.x < 64) bs[threadIdx.x] = b3[threadIdx.x];
    __syncthreads();
    int warp = (blockIdx.x * blockDim.x + threadIdx.x) >> 5;
    int lane = threadIdx.x & 31;
    if (warp >= N) return;
    float2 agg = gather64(h2, csr, offs[warp], deg[warp], lane);
    float2 own = *(const float2*)(h2 + (size_t)warp * 64 + lane * 2);
    float sx = own.x + agg.x;
    float sy = own.y + agg.y;
    float o0 = bs[2 * lane], o1 = bs[2 * lane + 1];
    const float2* Wv = (const float2*)Ws;
    #pragma unroll
    for (int k = 0; k < 64; k++) {
        float bv = __shfl_sync(FULL, (k & 1) ? sy : sx, k >> 1);
        float2 w = Wv[k * 32 + lane];
        o0 = fmaf(bv, w.x, o0);
        o1 = fmaf(bv, w.y, o1);
    }
    o0 = elu(o0);
    o1 = elu(o1);
    int g = batch[warp];
    red2(pool + (size_t)g * 64 + lane * 2, o0, o1);
    if (lane == 0) atomicAdd(&cnt[g], 1.0f);
}

// ------------------------- final 64->64->32->1 MLP --------------------------
__global__ void final_mlp_kernel(const float* __restrict__ pool,
                                 const float* __restrict__ cnt,
                                 const float* __restrict__ Wf1, const float* __restrict__ bf1,
                                 const float* __restrict__ Wf2, const float* __restrict__ bf2,
                                 const float* __restrict__ Wf3, const float* __restrict__ bf3,
                                 float* __restrict__ out, int G) {
    __shared__ float W1s[64 * 64];
    __shared__ float W2s[64 * 32];
    __shared__ float W3s[32];
    __shared__ float b1s[64];
    __shared__ float b2s[32];
    for (int i = threadIdx.x; i < 64 * 64; i += 256) W1s[i] = Wf1[i];
    for (int i = threadIdx.x; i < 64 * 32; i += 256) W2s[i] = Wf2[i];
    if (threadIdx.x < 32) W3s[threadIdx.x] = Wf3[threadIdx.x];
    if (threadIdx.x < 64) b1s[threadIdx.x] = bf1[threadIdx.x];
    if (threadIdx.x < 32) b2s[threadIdx.x] = bf2[threadIdx.x];
    __syncthreads();

    int g = blockIdx.x * blockDim.x + threadIdx.x;
    if (g >= G) return;

    float inv = 1.0f / fmaxf(cnt[g], 1.0f);
    float m[64];
    #pragma unroll
    for (int k = 0; k < 64; k++) m[k] = pool[(size_t)g * 64 + k] * inv;

    float h2v[32];
    #pragma unroll
    for (int j = 0; j < 32; j++) h2v[j] = b2s[j];

    for (int fo = 0; fo < 64; fo++) {
        float a = b1s[fo];
        #pragma unroll
        for (int k = 0; k < 64; k++) a = fmaf(m[k], W1s[k * 64 + fo], a);
        a = elu(a);
        #pragma unroll
        for (int j = 0; j < 32; j++) h2v[j] = fmaf(a, W2s[fo * 32 + j], h2v[j]);
    }

    float o = bf3[0];
    #pragma unroll
    for (int j = 0; j < 32; j++) {
        float t = elu(h2v[j]);
        o = fmaf(t, W3s[j], o);
    }
    out[g] = o;
}

// ---------------------------------------------------------------------------
extern "C" void kernel_launch(void* const* d_in, const int* in_sizes, int n_in,
                              void* d_out, int out_size) {
    const float* x     = (const float*)d_in[0];
    const int*   ei    = (const int*)d_in[1];
    const int*   batch = (const int*)d_in[2];
    const float* W1  = (const float*)d_in[4];
    const float* b1  = (const float*)d_in[5];
    const float* W2  = (const float*)d_in[6];
    const float* b2  = (const float*)d_in[7];
    const float* W3  = (const float*)d_in[8];
    const float* b3  = (const float*)d_in[9];
    const float* Wf1 = (const float*)d_in[10];
    const float* bf1 = (const float*)d_in[11];
    const float* Wf2 = (const float*)d_in[12];
    const float* bf2 = (const float*)d_in[13];
    const float* Wf3 = (const float*)d_in[14];
    const float* bf3 = (const float*)d_in[15];

    const int N = in_sizes[0] / 64;
    const int E = in_sizes[1] / 2;
    const int G = out_size;

    const int* src = ei;
    const int* dst = ei + E;

    float *bufA, *bufB, *pool, *cnt;
    int *deg, *offs, *cursor, *bsums, *csr;
    cudaGetSymbolAddress((void**)&bufA,   g_bufA);
    cudaGetSymbolAddress((void**)&bufB,   g_bufB);
    cudaGetSymbolAddress((void**)&pool,   g_pool);
    cudaGetSymbolAddress((void**)&cnt,    g_cnt);
    cudaGetSymbolAddress((void**)&deg,    g_deg);
    cudaGetSymbolAddress((void**)&offs,   g_offs);
    cudaGetSymbolAddress((void**)&cursor, g_cursor);
    cudaGetSymbolAddress((void**)&bsums,  g_bsums);
    cudaGetSymbolAddress((void**)&csr,    g_csr);

    const int TPB = 256;
    const int eblk = (E + TPB - 1) / TPB;
    const int nblk1024 = (N + 1023) / 1024;
    const int nodeblk = (N + 7) / 8;

    // ---- CSR build (by dst) ----
    cudaMemsetAsync(deg, 0, (size_t)N * sizeof(int));
    count_deg_kernel<<<eblk, TPB>>>(dst, deg, E);
    scan_block_kernel<<<nblk1024, 1024>>>(deg, offs, bsums, N);
    scan_sums_kernel<<<1, 32>>>(bsums, nblk1024);
    add_off_kernel<<<(N + TPB - 1) / TPB, TPB>>>(offs, cursor, bsums, N);
    fill_csr_kernel<<<eblk, TPB>>>(src, dst, cursor, csr, E);

    // ---- Layer 1 (transform-first): y = x@W1; h1 = elu(y + A@y + b1) ----
    linear1_kernel<<<nodeblk, TPB>>>(x, W1, bufA, N);
    gin_layer1_kernel<<<nodeblk, TPB>>>(bufA, offs, deg, csr, b1, bufB, N);

    // ---- Layer 2 ----
    gin_layer2_kernel<<<nodeblk, TPB>>>(bufB, offs, deg, csr, W2, b2, bufA, N);

    // ---- Layer 3 + pooling ----
    cudaMemsetAsync(pool, 0, (size_t)G * 64 * sizeof(float));
    cudaMemsetAsync(cnt,  0, (size_t)G * sizeof(float));
    gin_layer3_pool_kernel<<<nodeblk, TPB>>>(bufA, offs, deg, csr, W3, b3, batch,
                                             pool, cnt, N);

    // ---- Final MLP ----
    final_mlp_kernel<<<(G + TPB - 1) / TPB, TPB>>>(pool, cnt, Wf1, bf1, Wf2, bf2,
                                                   Wf3, bf3, (float*)d_out, G);
}